// round 1
// baseline (speedup 1.0000x reference)
#include <cuda_runtime.h>

// Problem constants (fixed shapes)
#define N_SAMPLES 1024
#define L_LAYERS  60
#define C_CH      42
#define K_G       8
#define H_ODC     64
#define NOUT      336      // C*K
#define H_SCC     16
#define LC        2520     // L*C
#define NTHREADS  352
#define SOLAR_C   1361.0f
#define EPSV      1e-6f

// Output offsets (tuple arrays flattened C-order, concatenated in order)
#define OFF_FDIR 0
#define OFF_FDIF (N_SAMPLES*61)
#define OFF_FUP  (2*N_SAMPLES*61)
#define OFF_FABS (3*N_SAMPLES*61)
#define OFF_RTOA (OFF_FABS + N_SAMPLES*60)
#define OFF_SDIR (OFF_RTOA + N_SAMPLES)
#define OFF_SDIF (OFF_SDIR + N_SAMPLES*60)
#define OFF_TDIR (OFF_SDIF + N_SAMPLES*60)
#define OFF_TDIF (OFF_TDIR + N_SAMPLES*60)

struct Smem {
    float w2p[336*68];     // od_w2 padded rows (68 floats) for conflict-free LDS.128
    float arrs[9*2520];    // slot0 tau/rb_dir, 1 td/a, 2 sd/D, 3 rd/up, 4 Td/abs,
                           // 5 Rd, 6 tdif/rb_dif, 7 d_seq, 8 (1-tf)(e0f+e1f)
    float xs[600];         // x_layers row for this sample
    float b2[336];
    float b1[64];
    float w1[128];
    float scw1_0[16];
    float beff_dir[16];
    float beff_dif[16];
    float scw2[48];
    float scb2[3];
    float cs[42];
    float cs_sum;
    float scratch[64];
};

__device__ __forceinline__ float softplus_f(float x) {
    return fmaxf(x, 0.f) + __logf(1.f + __expf(-fabsf(x)));
}

__global__ __launch_bounds__(NTHREADS, 1)
void radnet_kernel(const float* __restrict__ x_layers,
                   const float* __restrict__ x_surface,
                   const float* __restrict__ w_mu,
                   const float* __restrict__ w_spec,
                   const float* __restrict__ od_w1,
                   const float* __restrict__ od_b1,
                   const float* __restrict__ od_w2,
                   const float* __restrict__ od_b2,
                   const float* __restrict__ sc_w1,
                   const float* __restrict__ sc_b1,
                   const float* __restrict__ sc_w2,
                   const float* __restrict__ sc_b2,
                   float* __restrict__ out)
{
    extern __shared__ __align__(16) char smem_raw[];
    Smem* S = reinterpret_cast<Smem*>(smem_raw);
    const int tid = threadIdx.x;
    const int n = blockIdx.x;

    // per-sample / global scalars
    const float mu_direct = __ldg(&x_surface[n*5 + 0]);
    const float rs_dir    = __ldg(&x_surface[n*5 + 1]);
    const float rs_dif    = __ldg(&x_surface[n*5 + 2]);
    const float wmu       = __ldg(&w_mu[0]);
    const float mu_dif0   = 1.f / (1.f + __expf(-wmu));
    const float inv_mud   = 1.f / (mu_direct + EPSV);
    const float inv_muf   = 1.f / (mu_dif0 + EPSV);

    // ---------------- setup: stage weights + inputs into smem ----------------
    {
        const float4* src = reinterpret_cast<const float4*>(od_w2);
        float4* dst = reinterpret_cast<float4*>(S->w2p);
        for (int i = tid; i < 5376; i += NTHREADS) {
            int o = i >> 4, jj = i & 15;
            dst[o*17 + jj] = src[i];
        }
        const float4* xsrc = reinterpret_cast<const float4*>(x_layers + (size_t)n * 600);
        float4* xdst = reinterpret_cast<float4*>(S->xs);
        for (int i = tid; i < 150; i += NTHREADS) xdst[i] = xsrc[i];
        for (int i = tid; i < 336; i += NTHREADS) S->b2[i] = od_b2[i];
        if (tid < 64)  S->b1[tid] = od_b1[tid];
        if (tid < 128) S->w1[tid] = od_w1[tid];
        if (tid < 16) {
            float w1c = sc_w1[tid*2 + 1];
            float b   = sc_b1[tid];
            S->scw1_0[tid]   = sc_w1[tid*2];
            S->beff_dir[tid] = fmaf(w1c, mu_direct, b);
            S->beff_dif[tid] = fmaf(w1c, mu_dif0, b);
        }
        if (tid >= 32 && tid < 80) S->scw2[tid-32] = sc_w2[tid-32];
        if (tid >= 80 && tid < 83) S->scb2[tid-80] = sc_b2[tid-80];
        if (tid == NTHREADS-1) {
            float m = -1e30f;
            for (int c = 0; c < C_CH; c++) m = fmaxf(m, w_spec[c]);
            float s = 0.f;
            float tmp[C_CH];
            for (int c = 0; c < C_CH; c++) { float e = __expf(w_spec[c]-m); tmp[c] = e; s += e; }
            float inv = 1.f / s;
            float cssum = 0.f;
            for (int c = 0; c < C_CH; c++) { float v = tmp[c]*inv; S->cs[c] = v; cssum += v; }
            S->cs_sum = cssum;
        }
    }
    __syncthreads();

    // ---------------- phase 1a: hidden layer h[60][64] ----------------
    float* h_all = S->arrs + 2520;         // lives in slots 1-2 region (free until phase 2)
    for (int i = tid; i < 3840; i += NTHREADS) {
        int l = i >> 6, j = i & 63;
        float pre = fmaf(S->w1[j*2],   S->xs[l*10],
                    fmaf(S->w1[j*2+1], S->xs[l*10+1], S->b1[j]));
        h_all[i] = softplus_f(pre);
    }
    __syncthreads();

    // ---------------- phase 1b: sigma = softplus(W2 h + b2); tau_tot ----------------
    float* tau = S->arrs;                  // slot0
    if (tid < NOUT) {
        const int o = tid;
        const int k = o & 7;
        const int lane = tid & 31;
        const unsigned mask8 = 0xFFu << (lane & 24);
        const float4* w2row = reinterpret_cast<const float4*>(S->w2p) + o*17;
        const float4* h4 = reinterpret_cast<const float4*>(h_all);
        const float b2o = S->b2[o];
        #pragma unroll 1
        for (int ch = 0; ch < 4; ch++) {
            const int l0 = ch * 15;
            float acc[15];
            #pragma unroll
            for (int ll = 0; ll < 15; ll++) acc[ll] = 0.f;
            #pragma unroll
            for (int jj = 0; jj < 16; jj++) {
                float4 w = w2row[jj];
                #pragma unroll
                for (int ll = 0; ll < 15; ll++) {
                    float4 h = h4[(l0+ll)*16 + jj];
                    acc[ll] = fmaf(w.x, h.x, fmaf(w.y, h.y, fmaf(w.z, h.z, fmaf(w.w, h.w, acc[ll]))));
                }
            }
            #pragma unroll
            for (int ll = 0; ll < 15; ll++) {
                int l = l0 + ll;
                float sig = softplus_f(acc[ll] + b2o);
                float v = sig * S->xs[l*10 + 2 + k];
                v += __shfl_xor_sync(mask8, v, 1);
                v += __shfl_xor_sync(mask8, v, 2);
                v += __shfl_xor_sync(mask8, v, 4);
                if (k == 0) tau[l*42 + (o >> 3)] = v;
            }
        }
    }
    __syncthreads();

    // ---------------- phase 2: per-(l,c) physics + split MLPs ----------------
    float* s_td = S->arrs + 1*2520;
    float* s_sd = S->arrs + 2*2520;
    float* s_rd = S->arrs + 3*2520;
    float* s_Td = S->arrs + 4*2520;
    float* s_Rd = S->arrs + 5*2520;
    float* s_tf = S->arrs + 6*2520;
    float* s_es = S->arrs + 8*2520;  // (1-tf)*(e0f+e1f)
    {
        float tt[8];
        #pragma unroll
        for (int r = 0; r < 8; r++) {
            int idx = tid + r*NTHREADS;
            tt[r] = tau[idx < LC ? idx : 0];
        }
        const float b20 = S->scb2[0], b21 = S->scb2[1], b22 = S->scb2[2];
        float a0d[8], a1d[8], a2d[8], a0f[8], a1f[8], a2f[8];
        #pragma unroll
        for (int r = 0; r < 8; r++) {
            a0d[r]=b20; a1d[r]=b21; a2d[r]=b22;
            a0f[r]=b20; a1f[r]=b21; a2f[r]=b22;
        }
        #pragma unroll
        for (int j = 0; j < 16; j++) {
            float w0  = S->scw1_0[j];
            float bd  = S->beff_dir[j];
            float bf  = S->beff_dif[j];
            float w20 = S->scw2[j], w21 = S->scw2[16+j], w22 = S->scw2[32+j];
            #pragma unroll
            for (int r = 0; r < 8; r++) {
                float hp = w0 * tt[r];
                float hd = fmaxf(hp + bd, 0.f);
                float hf = fmaxf(hp + bf, 0.f);
                a0d[r] = fmaf(w20, hd, a0d[r]);
                a1d[r] = fmaf(w21, hd, a1d[r]);
                a2d[r] = fmaf(w22, hd, a2d[r]);
                a0f[r] = fmaf(w20, hf, a0f[r]);
                a1f[r] = fmaf(w21, hf, a1f[r]);
                a2f[r] = fmaf(w22, hf, a2f[r]);
            }
        }
        #pragma unroll
        for (int r = 0; r < 8; r++) {
            int idx = tid + r*NTHREADS;
            if (idx >= LC) break;
            float td = __expf(-tt[r]*inv_mud);
            float tf = __expf(-tt[r]*inv_muf);
            float m  = fmaxf(a0d[r], fmaxf(a1d[r], a2d[r]));
            float x0 = __expf(a0d[r]-m), x1 = __expf(a1d[r]-m), x2 = __expf(a2d[r]-m);
            float inv = 1.f/(x0+x1+x2);
            float e0d = x0*inv, e1d = x1*inv;
            m  = fmaxf(a0f[r], fmaxf(a1f[r], a2f[r]));
            x0 = __expf(a0f[r]-m); x1 = __expf(a1f[r]-m); x2 = __expf(a2f[r]-m);
            inv = 1.f/(x0+x1+x2);
            float e0f = x0*inv, e1f = x1*inv;
            float omtd = 1.f - td, omtf = 1.f - tf;
            s_td[idx] = td;
            s_sd[idx] = omtd*e0d;
            s_rd[idx] = omtd*e1d;
            s_Td[idx] = fmaf(omtf, e0f, tf);
            s_Rd[idx] = omtf*e1f;
            s_tf[idx] = tf;
            s_es[idx] = omtf*(e0f+e1f);
        }
    }
    __syncthreads();

    // ---------------- phase 2b: per-layer channel sums (s_*, t_*) ----------------
    if (tid < 240) {
        int arr = tid / 60, l = tid % 60;
        int base = l*42;
        float s = 0.f;
        if (arr == 0) {
            for (int c = 0; c < C_CH; c++) s = fmaf(s_sd[base+c] + s_rd[base+c], S->cs[c], s);
            out[OFF_SDIR + n*60 + l] = s;
        } else if (arr == 1) {
            for (int c = 0; c < C_CH; c++) s = fmaf(s_es[base+c], S->cs[c], s);
            out[OFF_SDIF + n*60 + l] = s;
        } else if (arr == 2) {
            for (int c = 0; c < C_CH; c++) s = fmaf(s_td[base+c], S->cs[c], s);
            out[OFF_TDIR + n*60 + l] = s;
        } else {
            for (int c = 0; c < C_CH; c++) s = fmaf(s_tf[base+c], S->cs[c], s);
            out[OFF_TDIF + n*60 + l] = s;
        }
    }
    __syncthreads();

    // ---------------- phase 3 (backward scan) + phase 4 (forward scan) ----------------
    float* s_rbd = S->arrs;            // slot0 reuse (tau dead)
    float* s_rbf = S->arrs + 6*2520;   // slot6 reuse (tf consumed by 2b)
    float* s_dd  = S->arrs + 7*2520;
    if (tid < C_CH) {
        const int c = tid;
        float rbd = rs_dir, rbf = rs_dif;
        for (int l = 59; l >= 0; l--) {
            int idx = l*42 + c;
            float td = s_td[idx], sd = s_sd[idx], rd = s_rd[idx];
            float Td = s_Td[idx], Rd = s_Rd[idx];
            float dd = 1.f / (1.f - Rd*rbf);
            s_rbd[idx] = rbd; s_rbf[idx] = rbf; s_dd[idx] = dd;
            float rad = rd + Td*dd*(td*rbd + sd*rbf);
            float raf = Rd + Td*Td*dd*rbf;
            rbd = rad; rbf = raf;
        }
        S->scratch[c] = rbd * S->cs[c];  // r_toa contribution

        float fdir = S->cs[c] * mu_direct * SOLAR_C;
        float fdif = 0.f;
        for (int l = 0; l < 60; l++) {
            int idx = l*42 + c;
            float td = s_td[idx], sd = s_sd[idx], rd = s_rd[idx];
            float Td = s_Td[idx], Rd = s_Rd[idx];
            float rb0 = s_rbd[idx], rb1 = s_rbf[idx], dd = s_dd[idx];
            float a  = td * fdir;
            float D  = dd * (Td*fdif + sd*fdir + Rd*rb0*a);
            float U  = rb0*a + rb1*D;
            float up = rd*fdir + Rd*fdif + Td*U;
            float ab = fdir + fdif + U - a - D - up;
            s_td[idx] = a; s_sd[idx] = D; s_rd[idx] = up; s_Td[idx] = ab;
            fdir = a; fdif = D;
        }
    }
    __syncthreads();

    // ---------------- phase 5: flux reductions over channels ----------------
    if (tid < 240) {
        int arr = tid / 60, l = tid % 60;
        const float* src = S->arrs + (arr+1)*2520 + l*42;  // a, D, up, abs
        float s = 0.f;
        #pragma unroll 6
        for (int c = 0; c < C_CH; c++) s += src[c];
        if (arr == 0)      { out[OFF_FDIR + n*61 + l + 1] = s; if (l == 59) S->scratch[48] = s; }
        else if (arr == 1) { out[OFF_FDIF + n*61 + l + 1] = s; if (l == 59) S->scratch[49] = s; }
        else if (arr == 2) { out[OFF_FUP  + n*61 + l] = s; }
        else               { out[OFF_FABS + n*60 + l] = s; }
    }
    __syncthreads();

    if (tid == 0) {
        out[OFF_FDIR + n*61]      = mu_direct * SOLAR_C * S->cs_sum;
        out[OFF_FDIF + n*61]      = 0.f;
        out[OFF_FUP  + n*61 + 60] = rs_dir * S->scratch[48] + rs_dif * S->scratch[49];
        float rt = 0.f;
        for (int c = 0; c < C_CH; c++) rt += S->scratch[c];
        out[OFF_RTOA + n] = rt;
    }
}

extern "C" void kernel_launch(void* const* d_in, const int* in_sizes, int n_in,
                              void* d_out, int out_size) {
    (void)in_sizes; (void)n_in; (void)out_size;
    cudaFuncSetAttribute(radnet_kernel, cudaFuncAttributeMaxDynamicSharedMemorySize,
                         (int)sizeof(Smem));
    radnet_kernel<<<N_SAMPLES, NTHREADS, sizeof(Smem)>>>(
        (const float*)d_in[0],  (const float*)d_in[1],  (const float*)d_in[2],
        (const float*)d_in[3],  (const float*)d_in[4],  (const float*)d_in[5],
        (const float*)d_in[6],  (const float*)d_in[7],  (const float*)d_in[8],
        (const float*)d_in[9],  (const float*)d_in[10], (const float*)d_in[11],
        (float*)d_out);
}

// round 3
// speedup vs baseline: 1.1462x; 1.1462x over previous
#include <cuda_runtime.h>

// Problem constants (fixed shapes)
#define N_SAMPLES 1024
#define L_LAYERS  60
#define C_CH      42
#define K_G       8
#define NOUT      336      // C*K
#define LC        2520     // L*C
#define NTHREADS  352
#define SOLAR_C   1361.0f
#define EPSV      1e-6f

// Output offsets (tuple arrays flattened C-order, concatenated in order)
#define OFF_FDIR 0
#define OFF_FDIF (N_SAMPLES*61)
#define OFF_FUP  (2*N_SAMPLES*61)
#define OFF_FABS (3*N_SAMPLES*61)
#define OFF_RTOA (OFF_FABS + N_SAMPLES*60)
#define OFF_SDIR (OFF_RTOA + N_SAMPLES)
#define OFF_SDIF (OFF_SDIR + N_SAMPLES*60)
#define OFF_TDIR (OFF_SDIF + N_SAMPLES*60)
#define OFF_TDIF (OFF_TDIR + N_SAMPLES*60)

// Smem plane usage over time (8 planes of 2520):
//  0: tau     -> td  -> a          (phase1b -> phase2 -> phase4)
//  1: (h lo)  -> sd  -> D
//  2: (h hi)  -> rd  -> up
//  3:            Td  -> abs
//  4:            Rd
//  5:            tf  -> rb_dir     (tf consumed by 2b before phase3)
//  6:            es  -> rb_dif     (es consumed by 2b before phase3)
//  7:            (unused spare)
struct Smem {
    float arrs[8*2520];
    float xs[600];         // x_layers row for this sample
    float b2[336];
    float b1[64];
    float w1[128];
    float scw1_0[16];
    float beff_dir[16];
    float beff_dif[16];
    float scw2[48];
    float scb2[4];
    float cs[42];
    float cs_sum;
    float scratch[64];
};

__device__ __forceinline__ float softplus_f(float x) {
    return fmaxf(x, 0.f) + __logf(1.f + __expf(-fabsf(x)));
}
__device__ __forceinline__ float frcp(float x) {
    float r; asm("rcp.approx.ftz.f32 %0, %1;" : "=f"(r) : "f"(x)); return r;
}
// rcp.approx + one Newton-Raphson step: full fp32 accuracy, no FP div latency
__device__ __forceinline__ float frcp_nr(float x) {
    float r = frcp(x);
    return r * (2.f - x * r);
}

__global__ __launch_bounds__(NTHREADS, 2)
void radnet_kernel(const float* __restrict__ x_layers,
                   const float* __restrict__ x_surface,
                   const float* __restrict__ w_mu,
                   const float* __restrict__ w_spec,
                   const float* __restrict__ od_w1,
                   const float* __restrict__ od_b1,
                   const float* __restrict__ od_w2,
                   const float* __restrict__ od_b2,
                   const float* __restrict__ sc_w1,
                   const float* __restrict__ sc_b1,
                   const float* __restrict__ sc_w2,
                   const float* __restrict__ sc_b2,
                   float* __restrict__ out)
{
    extern __shared__ __align__(16) char smem_raw[];
    Smem* S = reinterpret_cast<Smem*>(smem_raw);
    const int tid = threadIdx.x;
    const int n = blockIdx.x;

    const float mu_direct = __ldg(&x_surface[n*5 + 0]);
    const float rs_dir    = __ldg(&x_surface[n*5 + 1]);
    const float rs_dif    = __ldg(&x_surface[n*5 + 2]);
    const float wmu       = __ldg(&w_mu[0]);
    const float mu_dif0   = 1.f / (1.f + __expf(-wmu));
    const float inv_mud   = 1.f / (mu_direct + EPSV);
    const float inv_muf   = 1.f / (mu_dif0 + EPSV);

    // ---------------- setup: stage small weights + inputs into smem ----------------
    {
        const float4* xsrc = reinterpret_cast<const float4*>(x_layers + (size_t)n * 600);
        float4* xdst = reinterpret_cast<float4*>(S->xs);
        for (int i = tid; i < 150; i += NTHREADS) xdst[i] = xsrc[i];
        for (int i = tid; i < 336; i += NTHREADS) S->b2[i] = od_b2[i];
        if (tid < 64)  S->b1[tid] = od_b1[tid];
        if (tid >= 64 && tid < 192) S->w1[tid-64] = od_w1[tid-64];
        if (tid >= 192 && tid < 208) {
            int j = tid - 192;
            float w1c = sc_w1[j*2 + 1];
            float b   = sc_b1[j];
            S->scw1_0[j]   = sc_w1[j*2];
            S->beff_dir[j] = fmaf(w1c, mu_direct, b);
            S->beff_dif[j] = fmaf(w1c, mu_dif0, b);
        }
        if (tid >= 208 && tid < 256) S->scw2[tid-208] = sc_w2[tid-208];
        if (tid >= 256 && tid < 259) S->scb2[tid-256] = sc_b2[tid-256];
        if (tid == NTHREADS-1) {
            float m = -1e30f;
            for (int c = 0; c < C_CH; c++) m = fmaxf(m, w_spec[c]);
            float s = 0.f;
            float tmp[C_CH];
            for (int c = 0; c < C_CH; c++) { float e = __expf(w_spec[c]-m); tmp[c] = e; s += e; }
            float inv = 1.f / s;
            float cssum = 0.f;
            for (int c = 0; c < C_CH; c++) { float v = tmp[c]*inv; S->cs[c] = v; cssum += v; }
            S->cs_sum = cssum;
        }
    }
    __syncthreads();

    // ---------------- phase 1a: hidden layer h[60][64] (planes 1-2 region) ----------------
    float* h_all = S->arrs + 2520;
    for (int i = tid; i < 3840; i += NTHREADS) {
        int l = i >> 6, j = i & 63;
        float pre = fmaf(S->w1[j*2],   S->xs[l*10],
                    fmaf(S->w1[j*2+1], S->xs[l*10+1], S->b1[j]));
        h_all[i] = softplus_f(pre);
    }
    __syncthreads();

    // ---------------- phase 1b: sigma = softplus(od_w2 @ h + b2); tau_tot ----------------
    // Each of 336 threads owns output row o. od_w2 row read from L2 (shared across blocks).
    float* tau = S->arrs;  // plane 0
    if (tid < NOUT) {
        const int o = tid;
        const int k = o & 7;
        const int lane = tid & 31;
        const unsigned mask8 = 0xFFu << (lane & 24);
        const float4* w2g = reinterpret_cast<const float4*>(od_w2) + o*16;
        const float4* h4 = reinterpret_cast<const float4*>(h_all);
        const float b2o = S->b2[o];
        #pragma unroll 1
        for (int ch = 0; ch < 3; ch++) {
            const int l0 = ch * 20;
            float acc[20];
            #pragma unroll
            for (int ll = 0; ll < 20; ll++) acc[ll] = 0.f;
            float4 w = w2g[0];
            #pragma unroll 1
            for (int jj = 0; jj < 16; jj++) {
                float4 wn = (jj < 15) ? w2g[jj+1] : w;
                #pragma unroll
                for (int ll = 0; ll < 20; ll++) {
                    float4 h = h4[(l0+ll)*16 + jj];
                    acc[ll] = fmaf(w.x, h.x, fmaf(w.y, h.y, fmaf(w.z, h.z, fmaf(w.w, h.w, acc[ll]))));
                }
                w = wn;
            }
            #pragma unroll
            for (int ll = 0; ll < 20; ll++) {
                int l = l0 + ll;
                float sig = softplus_f(acc[ll] + b2o);
                float v = sig * S->xs[l*10 + 2 + k];
                v += __shfl_xor_sync(mask8, v, 1);
                v += __shfl_xor_sync(mask8, v, 2);
                v += __shfl_xor_sync(mask8, v, 4);
                if (k == 0) tau[l*42 + (o >> 3)] = v;
            }
        }
    }
    __syncthreads();

    // ---------------- phase 2: per-(l,c) physics + split MLPs (2 passes x rblk 4) ----------------
    float* s_td = S->arrs + 0*2520;
    float* s_sd = S->arrs + 1*2520;
    float* s_rd = S->arrs + 2*2520;
    float* s_Td = S->arrs + 3*2520;
    float* s_Rd = S->arrs + 4*2520;
    float* s_tf = S->arrs + 5*2520;
    float* s_es = S->arrs + 6*2520;  // (1-tf)*(e0f+e1f)
    #pragma unroll 1
    for (int pass = 0; pass < 2; pass++) {
        float tt[4];
        #pragma unroll
        for (int r = 0; r < 4; r++) {
            int idx = tid + (pass*4 + r)*NTHREADS;
            tt[r] = tau[idx < LC ? idx : 0];
        }
        const float b20 = S->scb2[0], b21 = S->scb2[1], b22 = S->scb2[2];
        float a0d[4], a1d[4], a2d[4], a0f[4], a1f[4], a2f[4];
        #pragma unroll
        for (int r = 0; r < 4; r++) {
            a0d[r]=b20; a1d[r]=b21; a2d[r]=b22;
            a0f[r]=b20; a1f[r]=b21; a2f[r]=b22;
        }
        #pragma unroll
        for (int j = 0; j < 16; j++) {
            float w0  = S->scw1_0[j];
            float bd  = S->beff_dir[j];
            float bf  = S->beff_dif[j];
            float w20 = S->scw2[j], w21 = S->scw2[16+j], w22 = S->scw2[32+j];
            #pragma unroll
            for (int r = 0; r < 4; r++) {
                float hp = w0 * tt[r];
                float hd = fmaxf(hp + bd, 0.f);
                float hf = fmaxf(hp + bf, 0.f);
                a0d[r] = fmaf(w20, hd, a0d[r]);
                a1d[r] = fmaf(w21, hd, a1d[r]);
                a2d[r] = fmaf(w22, hd, a2d[r]);
                a0f[r] = fmaf(w20, hf, a0f[r]);
                a1f[r] = fmaf(w21, hf, a1f[r]);
                a2f[r] = fmaf(w22, hf, a2f[r]);
            }
        }
        #pragma unroll
        for (int r = 0; r < 4; r++) {
            int idx = tid + (pass*4 + r)*NTHREADS;
            if (idx >= LC) break;
            float td = __expf(-tt[r]*inv_mud);
            float tf = __expf(-tt[r]*inv_muf);
            float m  = fmaxf(a0d[r], fmaxf(a1d[r], a2d[r]));
            float x0 = __expf(a0d[r]-m), x1 = __expf(a1d[r]-m), x2 = __expf(a2d[r]-m);
            float inv = frcp(x0+x1+x2);
            float e0d = x0*inv, e1d = x1*inv;
            m  = fmaxf(a0f[r], fmaxf(a1f[r], a2f[r]));
            x0 = __expf(a0f[r]-m); x1 = __expf(a1f[r]-m); x2 = __expf(a2f[r]-m);
            inv = frcp(x0+x1+x2);
            float e0f = x0*inv, e1f = x1*inv;
            float omtd = 1.f - td, omtf = 1.f - tf;
            s_td[idx] = td;                      // overwrites tau in place (own idx)
            s_sd[idx] = omtd*e0d;
            s_rd[idx] = omtd*e1d;
            s_Td[idx] = fmaf(omtf, e0f, tf);
            s_Rd[idx] = omtf*e1f;
            s_tf[idx] = tf;
            s_es[idx] = omtf*(e0f+e1f);
        }
    }
    __syncthreads();

    // ---------------- phase 2b: per-layer channel sums (s_*, t_*) ----------------
    if (tid < 240) {
        int arr = tid / 60, l = tid % 60;
        int base = l*42;
        float s = 0.f;
        if (arr == 0) {
            for (int c = 0; c < C_CH; c++) s = fmaf(s_sd[base+c] + s_rd[base+c], S->cs[c], s);
            out[OFF_SDIR + n*60 + l] = s;
        } else if (arr == 1) {
            for (int c = 0; c < C_CH; c++) s = fmaf(s_es[base+c], S->cs[c], s);
            out[OFF_SDIF + n*60 + l] = s;
        } else if (arr == 2) {
            for (int c = 0; c < C_CH; c++) s = fmaf(s_td[base+c], S->cs[c], s);
            out[OFF_TDIR + n*60 + l] = s;
        } else {
            for (int c = 0; c < C_CH; c++) s = fmaf(s_tf[base+c], S->cs[c], s);
            out[OFF_TDIF + n*60 + l] = s;
        }
    }
    __syncthreads();

    // ---------------- phase 3 (backward scan) + phase 4 (forward scan) ----------------
    float* s_rbd = S->arrs + 5*2520;   // reuse tf plane (consumed by 2b)
    float* s_rbf = S->arrs + 6*2520;   // reuse es plane (consumed by 2b)
    if (tid < C_CH) {
        const int c = tid;
        float rbd = rs_dir, rbf = rs_dif;
        for (int l = 59; l >= 0; l--) {
            int idx = l*42 + c;
            float td = s_td[idx], sd = s_sd[idx], rd = s_rd[idx];
            float Td = s_Td[idx], Rd = s_Rd[idx];
            float dd = frcp_nr(1.f - Rd*rbf);
            s_rbd[idx] = rbd; s_rbf[idx] = rbf;
            float rad = rd + Td*dd*(td*rbd + sd*rbf);
            float raf = Rd + Td*Td*dd*rbf;
            rbd = rad; rbf = raf;
        }
        S->scratch[c] = rbd * S->cs[c];  // r_toa contribution

        float fdir = S->cs[c] * mu_direct * SOLAR_C;
        float fdif = 0.f;
        for (int l = 0; l < 60; l++) {
            int idx = l*42 + c;
            float td = s_td[idx], sd = s_sd[idx], rd = s_rd[idx];
            float Td = s_Td[idx], Rd = s_Rd[idx];
            float rb0 = s_rbd[idx], rb1 = s_rbf[idx];
            float dd = frcp_nr(1.f - Rd*rb1);
            float a  = td * fdir;
            float D  = dd * (Td*fdif + sd*fdir + Rd*rb0*a);
            float U  = rb0*a + rb1*D;
            float up = rd*fdir + Rd*fdif + Td*U;
            float ab = fdir + fdif + U - a - D - up;
            s_td[idx] = a; s_sd[idx] = D; s_rd[idx] = up; s_Td[idx] = ab;
            fdir = a; fdif = D;
        }
    }
    __syncthreads();

    // ---------------- phase 5: flux reductions over channels ----------------
    if (tid < 240) {
        int arr = tid / 60, l = tid % 60;
        const float* src = S->arrs + arr*2520 + l*42;  // a, D, up, abs
        float s = 0.f;
        #pragma unroll 6
        for (int c = 0; c < C_CH; c++) s += src[c];
        if (arr == 0)      { out[OFF_FDIR + n*61 + l + 1] = s; if (l == 59) S->scratch[48] = s; }
        else if (arr == 1) { out[OFF_FDIF + n*61 + l + 1] = s; if (l == 59) S->scratch[49] = s; }
        else if (arr == 2) { out[OFF_FUP  + n*61 + l] = s; }
        else               { out[OFF_FABS + n*60 + l] = s; }
    }
    __syncthreads();

    if (tid == 0) {
        out[OFF_FDIR + n*61]      = mu_direct * SOLAR_C * S->cs_sum;
        out[OFF_FDIF + n*61]      = 0.f;
        out[OFF_FUP  + n*61 + 60] = rs_dir * S->scratch[48] + rs_dif * S->scratch[49];
        float rt = 0.f;
        for (int c = 0; c < C_CH; c++) rt += S->scratch[c];
        out[OFF_RTOA + n] = rt;
    }
}

extern "C" void kernel_launch(void* const* d_in, const int* in_sizes, int n_in,
                              void* d_out, int out_size) {
    (void)in_sizes; (void)n_in; (void)out_size;
    cudaFuncSetAttribute(radnet_kernel, cudaFuncAttributeMaxDynamicSharedMemorySize,
                         (int)sizeof(Smem));
    radnet_kernel<<<N_SAMPLES, NTHREADS, sizeof(Smem)>>>(
        (const float*)d_in[0],  (const float*)d_in[1],  (const float*)d_in[2],
        (const float*)d_in[3],  (const float*)d_in[4],  (const float*)d_in[5],
        (const float*)d_in[6],  (const float*)d_in[7],  (const float*)d_in[8],
        (const float*)d_in[9],  (const float*)d_in[10], (const float*)d_in[11],
        (float*)d_out);
}

// round 4
// speedup vs baseline: 1.1926x; 1.0404x over previous
#include <cuda_runtime.h>

// Problem constants (fixed shapes)
#define N_SAMPLES 1024
#define L_LAYERS  60
#define C_CH      42
#define NOUT      336      // C*K
#define LC        2520     // L*C
#define NTHREADS  352
#define SOLAR_C   1361.0f
#define EPSV      1e-6f

// Output offsets (tuple arrays flattened C-order, concatenated in order)
#define OFF_FDIR 0
#define OFF_FDIF (N_SAMPLES*61)
#define OFF_FUP  (2*N_SAMPLES*61)
#define OFF_FABS (3*N_SAMPLES*61)
#define OFF_RTOA (OFF_FABS + N_SAMPLES*60)
#define OFF_SDIR (OFF_RTOA + N_SAMPLES)
#define OFF_SDIF (OFF_SDIR + N_SAMPLES*60)
#define OFF_TDIR (OFF_SDIF + N_SAMPLES*60)
#define OFF_TDIF (OFF_TDIR + N_SAMPLES*60)

// Smem plane usage over time (8 planes of 2520 floats):
//  0: tau     -> td  -> a          (phase1b -> phase2 -> phase4)
//  1: (h_t lo)-> sd  -> D
//  2: (h_t hi)-> rd  -> up
//  3:            Td  -> abs
//  4:            Rd
//  5:            tf  -> rb_dir     (tf consumed by 2b before phase3)
//  6:            es  -> rb_dif     (es consumed by 2b before phase3)
//  7:            (spare)
struct Smem {
    float arrs[8*2520];
    float xs[600];
    float b2[336];
    float b1[64];
    float w1[128];
    float scw1_0[16];
    float beff_dir[16];
    float beff_dif[16];
    float scw2[48];
    float scb2[4];
    float cs[42];
    float cs_sum;
    float scratch[64];
};

__device__ __forceinline__ float softplus_f(float x) {
    return fmaxf(x, 0.f) + __logf(1.f + __expf(-fabsf(x)));
}
__device__ __forceinline__ float frcp(float x) {
    float r; asm("rcp.approx.ftz.f32 %0, %1;" : "=f"(r) : "f"(x)); return r;
}
__device__ __forceinline__ float frcp_nr(float x) {
    float r = frcp(x);
    return r * (2.f - x * r);
}
// ---- packed f32x2 helpers (Blackwell sm_100a) ----
__device__ __forceinline__ unsigned long long dup2(float x) {
    unsigned long long r;
    asm("mov.b64 %0, {%1, %1};" : "=l"(r) : "f"(x));
    return r;
}
__device__ __forceinline__ unsigned long long pack2(float lo, float hi) {
    unsigned long long r;
    asm("mov.b64 %0, {%1, %2};" : "=l"(r) : "f"(lo), "f"(hi));
    return r;
}
__device__ __forceinline__ void unpack2(unsigned long long v, float& lo, float& hi) {
    asm("mov.b64 {%0, %1}, %2;" : "=f"(lo), "=f"(hi) : "l"(v));
}
__device__ __forceinline__ void ffma2(unsigned long long& d, unsigned long long a,
                                      unsigned long long b) {
    asm("fma.rn.f32x2 %0, %1, %2, %0;" : "+l"(d) : "l"(a), "l"(b));
}

__global__ __launch_bounds__(NTHREADS, 2)
void radnet_kernel(const float* __restrict__ x_layers,
                   const float* __restrict__ x_surface,
                   const float* __restrict__ w_mu,
                   const float* __restrict__ w_spec,
                   const float* __restrict__ od_w1,
                   const float* __restrict__ od_b1,
                   const float* __restrict__ od_w2,
                   const float* __restrict__ od_b2,
                   const float* __restrict__ sc_w1,
                   const float* __restrict__ sc_b1,
                   const float* __restrict__ sc_w2,
                   const float* __restrict__ sc_b2,
                   float* __restrict__ out)
{
    extern __shared__ __align__(16) char smem_raw[];
    Smem* S = reinterpret_cast<Smem*>(smem_raw);
    const int tid = threadIdx.x;
    const int n = blockIdx.x;

    const float mu_direct = __ldg(&x_surface[n*5 + 0]);
    const float rs_dir    = __ldg(&x_surface[n*5 + 1]);
    const float rs_dif    = __ldg(&x_surface[n*5 + 2]);
    const float wmu       = __ldg(&w_mu[0]);
    const float mu_dif0   = 1.f / (1.f + __expf(-wmu));
    const float inv_mud   = 1.f / (mu_direct + EPSV);
    const float inv_muf   = 1.f / (mu_dif0 + EPSV);

    // ---------------- setup ----------------
    {
        const float4* xsrc = reinterpret_cast<const float4*>(x_layers + (size_t)n * 600);
        float4* xdst = reinterpret_cast<float4*>(S->xs);
        for (int i = tid; i < 150; i += NTHREADS) xdst[i] = xsrc[i];
        for (int i = tid; i < 336; i += NTHREADS) S->b2[i] = od_b2[i];
        if (tid < 64)  S->b1[tid] = od_b1[tid];
        if (tid >= 64 && tid < 192) S->w1[tid-64] = od_w1[tid-64];
        if (tid >= 192 && tid < 208) {
            int j = tid - 192;
            float w1c = sc_w1[j*2 + 1];
            float b   = sc_b1[j];
            S->scw1_0[j]   = sc_w1[j*2];
            S->beff_dir[j] = fmaf(w1c, mu_direct, b);
            S->beff_dif[j] = fmaf(w1c, mu_dif0, b);
        }
        if (tid >= 208 && tid < 256) S->scw2[tid-208] = sc_w2[tid-208];
        if (tid >= 256 && tid < 259) S->scb2[tid-256] = sc_b2[tid-256];
        if (tid == NTHREADS-1) {
            float m = -1e30f;
            for (int c = 0; c < C_CH; c++) m = fmaxf(m, w_spec[c]);
            float s = 0.f;
            float tmp[C_CH];
            for (int c = 0; c < C_CH; c++) { float e = __expf(w_spec[c]-m); tmp[c] = e; s += e; }
            float inv = 1.f / s;
            float cssum = 0.f;
            for (int c = 0; c < C_CH; c++) { float v = tmp[c]*inv; S->cs[c] = v; cssum += v; }
            S->cs_sum = cssum;
        }
    }
    __syncthreads();

    // ---------------- phase 1a: hidden layer, TRANSPOSED h_t[j][l], row stride 64 ----
    float* h_t = S->arrs + 2520;   // 64*64 floats, planes 1-2
    for (int i = tid; i < 3840; i += NTHREADS) {
        int j = i / 60, l = i - j*60;
        float pre = fmaf(S->w1[j*2],   S->xs[l*10],
                    fmaf(S->w1[j*2+1], S->xs[l*10+1], S->b1[j]));
        h_t[j*64 + l] = softplus_f(pre);
    }
    __syncthreads();

    // ---------------- phase 1b: GEMM via packed FFMA2. 168 threads x 2 outputs ----
    float* tau = S->arrs;  // plane 0
    if (tid < 168) {
        const int t = tid;
        const int k = t & 7;
        const unsigned mask8 = 0xFFu << ((t & 31) & 24);
        const float4* w2a4 = reinterpret_cast<const float4*>(od_w2) + t*16;
        const float4* w2b4 = w2a4 + 168*16;
        const float b2a = S->b2[t], b2b = S->b2[t+168];
        const int c1 = t >> 3, c2 = c1 + 21;
        const unsigned hbase = (unsigned)__cvta_generic_to_shared(h_t);
        #pragma unroll 1
        for (int chv = 0; chv < 3; chv++) {
            const int l0 = chv * 20;
            unsigned long long acc[10][2];
            #pragma unroll
            for (int q = 0; q < 10; q++) { acc[q][0] = 0ull; acc[q][1] = 0ull; }
            float4 wa = __ldg(&w2a4[0]), wb = __ldg(&w2b4[0]);
            #pragma unroll 1
            for (int j4 = 0; j4 < 16; j4++) {
                float4 wan = (j4 < 15) ? __ldg(&w2a4[j4+1]) : wa;
                float4 wbn = (j4 < 15) ? __ldg(&w2b4[j4+1]) : wb;
                #pragma unroll
                for (int jj = 0; jj < 4; jj++) {
                    const float wsa = (jj==0) ? wa.x : (jj==1) ? wa.y : (jj==2) ? wa.z : wa.w;
                    const float wsb = (jj==0) ? wb.x : (jj==1) ? wb.y : (jj==2) ? wb.z : wb.w;
                    unsigned long long wda = dup2(wsa);
                    unsigned long long wdb = dup2(wsb);
                    unsigned a = hbase + (unsigned)(((j4*4 + jj)*64 + l0) * 4);
                    #pragma unroll
                    for (int p = 0; p < 5; p++) {
                        unsigned long long h0, h1;
                        asm("ld.shared.v2.u64 {%0, %1}, [%2];"
                            : "=l"(h0), "=l"(h1) : "r"(a + (unsigned)(p*16)));
                        ffma2(acc[2*p  ][0], wda, h0);
                        ffma2(acc[2*p+1][0], wda, h1);
                        ffma2(acc[2*p  ][1], wdb, h0);
                        ffma2(acc[2*p+1][1], wdb, h1);
                    }
                }
                wa = wan; wb = wbn;
            }
            // epilogue: softplus, * con, 8-lane shuffle reduce, write tau
            #pragma unroll
            for (int q = 0; q < 10; q++) {
                float fa0, fa1, fb0, fb1;
                unpack2(acc[q][0], fa0, fa1);
                unpack2(acc[q][1], fb0, fb1);
                #pragma unroll
                for (int s2 = 0; s2 < 2; s2++) {
                    int l = l0 + 2*q + s2;
                    float fa = s2 ? fa1 : fa0;
                    float fb = s2 ? fb1 : fb0;
                    float con = S->xs[l*10 + 2 + k];
                    float va = softplus_f(fa + b2a) * con;
                    float vb = softplus_f(fb + b2b) * con;
                    va += __shfl_xor_sync(mask8, va, 1);
                    vb += __shfl_xor_sync(mask8, vb, 1);
                    va += __shfl_xor_sync(mask8, va, 2);
                    vb += __shfl_xor_sync(mask8, vb, 2);
                    va += __shfl_xor_sync(mask8, va, 4);
                    vb += __shfl_xor_sync(mask8, vb, 4);
                    if (k == 0) {
                        tau[l*42 + c1] = va;
                        tau[l*42 + c2] = vb;
                    }
                }
            }
        }
    }
    __syncthreads();

    // ---------------- phase 2: per-(l,c) physics + split MLPs (packed {dir,dif}) ----
    float* s_td = S->arrs + 0*2520;
    float* s_sd = S->arrs + 1*2520;
    float* s_rd = S->arrs + 2*2520;
    float* s_Td = S->arrs + 3*2520;
    float* s_Rd = S->arrs + 4*2520;
    float* s_tf = S->arrs + 5*2520;
    float* s_es = S->arrs + 6*2520;
    #pragma unroll 1
    for (int pass = 0; pass < 2; pass++) {
        float tt[4];
        #pragma unroll
        for (int r = 0; r < 4; r++) {
            int idx = tid + (pass*4 + r)*NTHREADS;
            tt[r] = tau[idx < LC ? idx : 0];
        }
        const float b20 = S->scb2[0], b21 = S->scb2[1], b22 = S->scb2[2];
        unsigned long long A0[4], A1[4], A2[4];
        #pragma unroll
        for (int r = 0; r < 4; r++) {
            A0[r] = dup2(b20); A1[r] = dup2(b21); A2[r] = dup2(b22);
        }
        #pragma unroll
        for (int j = 0; j < 16; j++) {
            float w0  = S->scw1_0[j];
            float bd  = S->beff_dir[j];
            float bf  = S->beff_dif[j];
            unsigned long long w20d = dup2(S->scw2[j]);
            unsigned long long w21d = dup2(S->scw2[16+j]);
            unsigned long long w22d = dup2(S->scw2[32+j]);
            #pragma unroll
            for (int r = 0; r < 4; r++) {
                float hp = w0 * tt[r];
                float hd = fmaxf(hp + bd, 0.f);
                float hf = fmaxf(hp + bf, 0.f);
                unsigned long long h2 = pack2(hd, hf);
                ffma2(A0[r], w20d, h2);
                ffma2(A1[r], w21d, h2);
                ffma2(A2[r], w22d, h2);
            }
        }
        #pragma unroll
        for (int r = 0; r < 4; r++) {
            int idx = tid + (pass*4 + r)*NTHREADS;
            if (idx >= LC) break;
            float a0d, a0f, a1d, a1f, a2d, a2f;
            unpack2(A0[r], a0d, a0f);
            unpack2(A1[r], a1d, a1f);
            unpack2(A2[r], a2d, a2f);
            float td = __expf(-tt[r]*inv_mud);
            float tf = __expf(-tt[r]*inv_muf);
            float m  = fmaxf(a0d, fmaxf(a1d, a2d));
            float x0 = __expf(a0d-m), x1 = __expf(a1d-m), x2 = __expf(a2d-m);
            float inv = frcp(x0+x1+x2);
            float e0d = x0*inv, e1d = x1*inv;
            m  = fmaxf(a0f, fmaxf(a1f, a2f));
            x0 = __expf(a0f-m); x1 = __expf(a1f-m); x2 = __expf(a2f-m);
            inv = frcp(x0+x1+x2);
            float e0f = x0*inv, e1f = x1*inv;
            float omtd = 1.f - td, omtf = 1.f - tf;
            s_td[idx] = td;
            s_sd[idx] = omtd*e0d;
            s_rd[idx] = omtd*e1d;
            s_Td[idx] = fmaf(omtf, e0f, tf);
            s_Rd[idx] = omtf*e1f;
            s_tf[idx] = tf;
            s_es[idx] = omtf*(e0f+e1f);
        }
    }
    __syncthreads();

    // ---------------- phase 2b: per-layer channel sums ----------------
    if (tid < 240) {
        int arr = tid / 60, l = tid % 60;
        int base = l*42;
        float s = 0.f;
        if (arr == 0) {
            for (int c = 0; c < C_CH; c++) s = fmaf(s_sd[base+c] + s_rd[base+c], S->cs[c], s);
            out[OFF_SDIR + n*60 + l] = s;
        } else if (arr == 1) {
            for (int c = 0; c < C_CH; c++) s = fmaf(s_es[base+c], S->cs[c], s);
            out[OFF_SDIF + n*60 + l] = s;
        } else if (arr == 2) {
            for (int c = 0; c < C_CH; c++) s = fmaf(s_td[base+c], S->cs[c], s);
            out[OFF_TDIR + n*60 + l] = s;
        } else {
            for (int c = 0; c < C_CH; c++) s = fmaf(s_tf[base+c], S->cs[c], s);
            out[OFF_TDIF + n*60 + l] = s;
        }
    }
    __syncthreads();

    // ---------------- phase 3 (backward scan) + phase 4 (forward scan) ----------------
    float* s_rbd = S->arrs + 5*2520;
    float* s_rbf = S->arrs + 6*2520;
    if (tid < C_CH) {
        const int c = tid;
        float rbd = rs_dir, rbf = rs_dif;
        for (int l = 59; l >= 0; l--) {
            int idx = l*42 + c;
            float td = s_td[idx], sd = s_sd[idx], rd = s_rd[idx];
            float Td = s_Td[idx], Rd = s_Rd[idx];
            float dd = frcp_nr(1.f - Rd*rbf);
            s_rbd[idx] = rbd; s_rbf[idx] = rbf;
            float rad = rd + Td*dd*(td*rbd + sd*rbf);
            float raf = Rd + Td*Td*dd*rbf;
            rbd = rad; rbf = raf;
        }
        S->scratch[c] = rbd * S->cs[c];

        float fdir = S->cs[c] * mu_direct * SOLAR_C;
        float fdif = 0.f;
        for (int l = 0; l < 60; l++) {
            int idx = l*42 + c;
            float td = s_td[idx], sd = s_sd[idx], rd = s_rd[idx];
            float Td = s_Td[idx], Rd = s_Rd[idx];
            float rb0 = s_rbd[idx], rb1 = s_rbf[idx];
            float dd = frcp_nr(1.f - Rd*rb1);
            float a  = td * fdir;
            float D  = dd * (Td*fdif + sd*fdir + Rd*rb0*a);
            float U  = rb0*a + rb1*D;
            float up = rd*fdir + Rd*fdif + Td*U;
            float ab = fdir + fdif + U - a - D - up;
            s_td[idx] = a; s_sd[idx] = D; s_rd[idx] = up; s_Td[idx] = ab;
            fdir = a; fdif = D;
        }
    }
    __syncthreads();

    // ---------------- phase 5: flux reductions over channels ----------------
    if (tid < 240) {
        int arr = tid / 60, l = tid % 60;
        const float* src = S->arrs + arr*2520 + l*42;
        float s = 0.f;
        #pragma unroll 6
        for (int c = 0; c < C_CH; c++) s += src[c];
        if (arr == 0)      { out[OFF_FDIR + n*61 + l + 1] = s; if (l == 59) S->scratch[48] = s; }
        else if (arr == 1) { out[OFF_FDIF + n*61 + l + 1] = s; if (l == 59) S->scratch[49] = s; }
        else if (arr == 2) { out[OFF_FUP  + n*61 + l] = s; }
        else               { out[OFF_FABS + n*60 + l] = s; }
    }
    __syncthreads();

    if (tid == 0) {
        out[OFF_FDIR + n*61]      = mu_direct * SOLAR_C * S->cs_sum;
        out[OFF_FDIF + n*61]      = 0.f;
        out[OFF_FUP  + n*61 + 60] = rs_dir * S->scratch[48] + rs_dif * S->scratch[49];
        float rt = 0.f;
        for (int c = 0; c < C_CH; c++) rt += S->scratch[c];
        out[OFF_RTOA + n] = rt;
    }
}

extern "C" void kernel_launch(void* const* d_in, const int* in_sizes, int n_in,
                              void* d_out, int out_size) {
    (void)in_sizes; (void)n_in; (void)out_size;
    cudaFuncSetAttribute(radnet_kernel, cudaFuncAttributeMaxDynamicSharedMemorySize,
                         (int)sizeof(Smem));
    radnet_kernel<<<N_SAMPLES, NTHREADS, sizeof(Smem)>>>(
        (const float*)d_in[0],  (const float*)d_in[1],  (const float*)d_in[2],
        (const float*)d_in[3],  (const float*)d_in[4],  (const float*)d_in[5],
        (const float*)d_in[6],  (const float*)d_in[7],  (const float*)d_in[8],
        (const float*)d_in[9],  (const float*)d_in[10], (const float*)d_in[11],
        (float*)d_out);
}

// round 5
// speedup vs baseline: 1.2547x; 1.0521x over previous
#include <cuda_runtime.h>

// Problem constants (fixed shapes)
#define N_SAMPLES 1024
#define L_LAYERS  60
#define C_CH      42
#define NOUT      336      // C*K
#define LC        2520     // L*C
#define NTHREADS  352
#define SOLAR_C   1361.0f
#define EPSV      1e-6f

// Output offsets (tuple arrays flattened C-order, concatenated in order)
#define OFF_FDIR 0
#define OFF_FDIF (N_SAMPLES*61)
#define OFF_FUP  (2*N_SAMPLES*61)
#define OFF_FABS (3*N_SAMPLES*61)
#define OFF_RTOA (OFF_FABS + N_SAMPLES*60)
#define OFF_SDIR (OFF_RTOA + N_SAMPLES)
#define OFF_SDIF (OFF_SDIR + N_SAMPLES*60)
#define OFF_TDIR (OFF_SDIF + N_SAMPLES*60)
#define OFF_TDIF (OFF_TDIR + N_SAMPLES*60)

// Smem plane usage over time (8 planes of 2520 floats):
//  0: tau     -> td  -> a          (phase1b -> phase2 -> phase4)
//  1: (h_t lo)-> sd  -> D
//  2: (h_t hi)-> rd  -> up
//  3:            Td  -> abs
//  4:            Rd
//  5:            tf  -> rb_dir
//  6:            es  -> rb_dif
//  7:            (spare)
struct Smem {
    float arrs[8*2520];
    float xs[600];
    float b2[336];
    float b1[64];
    float w1[128];
    float scw1_0[16];
    float beff_dir[16];
    float beff_dif[16];
    float scw2[48];
    float scb2[4];
    float cs[42];
    float cs_sum;
    float scratch[64];
};

__device__ __forceinline__ float softplus_f(float x) {
    return fmaxf(x, 0.f) + __logf(1.f + __expf(-fabsf(x)));
}
__device__ __forceinline__ float frcp(float x) {
    float r; asm("rcp.approx.ftz.f32 %0, %1;" : "=f"(r) : "f"(x)); return r;
}
__device__ __forceinline__ float frcp_nr(float x) {
    float r = frcp(x);
    return r * (2.f - x * r);
}
// ---- packed f32x2 helpers ----
__device__ __forceinline__ unsigned long long dup2(float x) {
    unsigned long long r;
    asm("mov.b64 %0, {%1, %1};" : "=l"(r) : "f"(x));
    return r;
}
__device__ __forceinline__ unsigned long long pack2(float lo, float hi) {
    unsigned long long r;
    asm("mov.b64 %0, {%1, %2};" : "=l"(r) : "f"(lo), "f"(hi));
    return r;
}
__device__ __forceinline__ void unpack2(unsigned long long v, float& lo, float& hi) {
    asm("mov.b64 {%0, %1}, %2;" : "=f"(lo), "=f"(hi) : "l"(v));
}
__device__ __forceinline__ void ffma2(unsigned long long& d, unsigned long long a,
                                      unsigned long long b) {
    asm("fma.rn.f32x2 %0, %1, %2, %0;" : "+l"(d) : "l"(a), "l"(b));
}

__global__ __launch_bounds__(NTHREADS, 2)
void radnet_kernel(const float* __restrict__ x_layers,
                   const float* __restrict__ x_surface,
                   const float* __restrict__ w_mu,
                   const float* __restrict__ w_spec,
                   const float* __restrict__ od_w1,
                   const float* __restrict__ od_b1,
                   const float* __restrict__ od_w2,
                   const float* __restrict__ od_b2,
                   const float* __restrict__ sc_w1,
                   const float* __restrict__ sc_b1,
                   const float* __restrict__ sc_w2,
                   const float* __restrict__ sc_b2,
                   float* __restrict__ out)
{
    extern __shared__ __align__(16) char smem_raw[];
    Smem* S = reinterpret_cast<Smem*>(smem_raw);
    const int tid = threadIdx.x;
    const int n = blockIdx.x;

    const float mu_direct = __ldg(&x_surface[n*5 + 0]);
    const float rs_dir    = __ldg(&x_surface[n*5 + 1]);
    const float rs_dif    = __ldg(&x_surface[n*5 + 2]);
    const float wmu       = __ldg(&w_mu[0]);
    const float mu_dif0   = 1.f / (1.f + __expf(-wmu));
    const float inv_mud   = 1.f / (mu_direct + EPSV);
    const float inv_muf   = 1.f / (mu_dif0 + EPSV);

    // ---------------- setup ----------------
    {
        const float4* xsrc = reinterpret_cast<const float4*>(x_layers + (size_t)n * 600);
        float4* xdst = reinterpret_cast<float4*>(S->xs);
        for (int i = tid; i < 150; i += NTHREADS) xdst[i] = xsrc[i];
        for (int i = tid; i < 336; i += NTHREADS) S->b2[i] = od_b2[i];
        if (tid < 64)  S->b1[tid] = od_b1[tid];
        if (tid >= 64 && tid < 192) S->w1[tid-64] = od_w1[tid-64];
        if (tid >= 192 && tid < 208) {
            int j = tid - 192;
            float w1c = sc_w1[j*2 + 1];
            float b   = sc_b1[j];
            S->scw1_0[j]   = sc_w1[j*2];
            S->beff_dir[j] = fmaf(w1c, mu_direct, b);
            S->beff_dif[j] = fmaf(w1c, mu_dif0, b);
        }
        if (tid >= 208 && tid < 256) S->scw2[tid-208] = sc_w2[tid-208];
        if (tid >= 256 && tid < 259) S->scb2[tid-256] = sc_b2[tid-256];
        if (tid == NTHREADS-1) {
            float m = -1e30f;
            for (int c = 0; c < C_CH; c++) m = fmaxf(m, w_spec[c]);
            float s = 0.f;
            float tmp[C_CH];
            for (int c = 0; c < C_CH; c++) { float e = __expf(w_spec[c]-m); tmp[c] = e; s += e; }
            float inv = 1.f / s;
            float cssum = 0.f;
            for (int c = 0; c < C_CH; c++) { float v = tmp[c]*inv; S->cs[c] = v; cssum += v; }
            S->cs_sum = cssum;
        }
    }
    __syncthreads();

    // ---------------- phase 1a: transposed hidden h_t[j][l], stride 64, l=60..63 zeroed ----
    float* h_t = S->arrs + 2520;   // 64*64 floats in planes 1-2
    for (int i = tid; i < 4096; i += NTHREADS) {
        int j = i >> 6, l = i & 63;
        float v = 0.f;
        if (l < 60) {
            float pre = fmaf(S->w1[j*2],   S->xs[l*10],
                        fmaf(S->w1[j*2+1], S->xs[l*10+1], S->b1[j]));
            v = softplus_f(pre);
        }
        h_t[i] = v;
    }
    __syncthreads();

    // ---------------- phase 1b: GEMM, 4 outputs x 16-layer tile per thread ----------------
    // thread t: og = (t>>2) mod 84 = c*2+half, lg = t&3 -> layers [lg*16, lg*16+16)
    // outputs o0 = c*8 + half*4 .. +3. Partner thread t^4 holds the other 4 k's of channel c.
    float* tau = S->arrs;  // plane 0
    {
        int og = tid >> 2; if (og >= 84) og -= 84;
        const int lg = tid & 3;
        const int c = og >> 1, half = og & 1;
        const int o0 = c*8 + half*4;
        const int l_base = lg << 4;
        const float4* w2r0 = reinterpret_cast<const float4*>(od_w2) + (o0    )*16;
        const float4* w2r1 = w2r0 + 16;
        const float4* w2r2 = w2r0 + 32;
        const float4* w2r3 = w2r0 + 48;
        float b2v[4];
        #pragma unroll
        for (int i = 0; i < 4; i++) b2v[i] = S->b2[o0+i];
        const unsigned hbase = (unsigned)__cvta_generic_to_shared(h_t) + (unsigned)(l_base*4);

        #pragma unroll 1
        for (int sub = 0; sub < 2; sub++) {
            const unsigned soff = (unsigned)(sub*32);   // 8 floats per sub-chunk
            unsigned long long acc0[4], acc1[4], acc2[4], acc3[4]; // [output][pair]
            #pragma unroll
            for (int p = 0; p < 4; p++) { acc0[p]=0ull; acc1[p]=0ull; acc2[p]=0ull; acc3[p]=0ull; }
            #pragma unroll 1
            for (int j4 = 0; j4 < 16; j4++) {
                float4 w0 = __ldg(&w2r0[j4]);
                float4 w1 = __ldg(&w2r1[j4]);
                float4 w2 = __ldg(&w2r2[j4]);
                float4 w3 = __ldg(&w2r3[j4]);
                #pragma unroll
                for (int jj = 0; jj < 4; jj++) {
                    const unsigned a = hbase + soff + (unsigned)((j4*4 + jj)*256);
                    unsigned long long h0, h1, h2, h3;
                    asm("ld.shared.v2.u64 {%0, %1}, [%2];"
                        : "=l"(h0), "=l"(h1) : "r"(a));
                    asm("ld.shared.v2.u64 {%0, %1}, [%2];"
                        : "=l"(h2), "=l"(h3) : "r"(a + 16u));
                    const float s0 = (jj==0)?w0.x:(jj==1)?w0.y:(jj==2)?w0.z:w0.w;
                    const float s1 = (jj==0)?w1.x:(jj==1)?w1.y:(jj==2)?w1.z:w1.w;
                    const float s2 = (jj==0)?w2.x:(jj==1)?w2.y:(jj==2)?w2.z:w2.w;
                    const float s3 = (jj==0)?w3.x:(jj==1)?w3.y:(jj==2)?w3.z:w3.w;
                    unsigned long long d0 = dup2(s0), d1 = dup2(s1);
                    unsigned long long d2 = dup2(s2), d3 = dup2(s3);
                    ffma2(acc0[0], d0, h0); ffma2(acc0[1], d0, h1);
                    ffma2(acc0[2], d0, h2); ffma2(acc0[3], d0, h3);
                    ffma2(acc1[0], d1, h0); ffma2(acc1[1], d1, h1);
                    ffma2(acc1[2], d1, h2); ffma2(acc1[3], d1, h3);
                    ffma2(acc2[0], d2, h0); ffma2(acc2[1], d2, h1);
                    ffma2(acc2[2], d2, h2); ffma2(acc2[3], d2, h3);
                    ffma2(acc3[0], d3, h0); ffma2(acc3[1], d3, h1);
                    ffma2(acc3[2], d3, h2); ffma2(acc3[3], d3, h3);
                }
            }
            // epilogue: per pair p -> layers la, lb
            #pragma unroll
            for (int p = 0; p < 4; p++) {
                const int la = l_base + sub*8 + 2*p;
                const int lb = la + 1;
                float f0a, f0b, f1a, f1b, f2a, f2b, f3a, f3b;
                unpack2(acc0[p], f0a, f0b);
                unpack2(acc1[p], f1a, f1b);
                unpack2(acc2[p], f2a, f2b);
                unpack2(acc3[p], f3a, f3b);
                float va = 0.f, vb = 0.f;
                if (la < 60) {
                    const float* cona = &S->xs[la*10 + 2 + half*4];
                    va = softplus_f(f0a + b2v[0]) * cona[0]
                       + softplus_f(f1a + b2v[1]) * cona[1]
                       + softplus_f(f2a + b2v[2]) * cona[2]
                       + softplus_f(f3a + b2v[3]) * cona[3];
                }
                if (lb < 60) {
                    const float* conb = &S->xs[lb*10 + 2 + half*4];
                    vb = softplus_f(f0b + b2v[0]) * conb[0]
                       + softplus_f(f1b + b2v[1]) * conb[1]
                       + softplus_f(f2b + b2v[2]) * conb[2]
                       + softplus_f(f3b + b2v[3]) * conb[3];
                }
                va += __shfl_xor_sync(0xFFFFFFFFu, va, 4);
                vb += __shfl_xor_sync(0xFFFFFFFFu, vb, 4);
                if (half == 0) {
                    if (la < 60) tau[la*42 + c] = va;
                    if (lb < 60) tau[lb*42 + c] = vb;
                }
            }
        }
    }
    __syncthreads();

    // ---------------- phase 2: per-(l,c) physics + split MLPs (packed {dir,dif}) ----
    float* s_td = S->arrs + 0*2520;
    float* s_sd = S->arrs + 1*2520;
    float* s_rd = S->arrs + 2*2520;
    float* s_Td = S->arrs + 3*2520;
    float* s_Rd = S->arrs + 4*2520;
    float* s_tf = S->arrs + 5*2520;
    float* s_es = S->arrs + 6*2520;
    #pragma unroll 1
    for (int pass = 0; pass < 2; pass++) {
        float tt[4];
        #pragma unroll
        for (int r = 0; r < 4; r++) {
            int idx = tid + (pass*4 + r)*NTHREADS;
            tt[r] = tau[idx < LC ? idx : 0];
        }
        const float b20 = S->scb2[0], b21 = S->scb2[1], b22 = S->scb2[2];
        unsigned long long A0[4], A1[4], A2[4];
        #pragma unroll
        for (int r = 0; r < 4; r++) {
            A0[r] = dup2(b20); A1[r] = dup2(b21); A2[r] = dup2(b22);
        }
        #pragma unroll
        for (int j = 0; j < 16; j++) {
            float w0  = S->scw1_0[j];
            float bd  = S->beff_dir[j];
            float bf  = S->beff_dif[j];
            unsigned long long w20d = dup2(S->scw2[j]);
            unsigned long long w21d = dup2(S->scw2[16+j]);
            unsigned long long w22d = dup2(S->scw2[32+j]);
            #pragma unroll
            for (int r = 0; r < 4; r++) {
                float hp = w0 * tt[r];
                float hd = fmaxf(hp + bd, 0.f);
                float hf = fmaxf(hp + bf, 0.f);
                unsigned long long h2 = pack2(hd, hf);
                ffma2(A0[r], w20d, h2);
                ffma2(A1[r], w21d, h2);
                ffma2(A2[r], w22d, h2);
            }
        }
        #pragma unroll
        for (int r = 0; r < 4; r++) {
            int idx = tid + (pass*4 + r)*NTHREADS;
            if (idx >= LC) break;
            float a0d, a0f, a1d, a1f, a2d, a2f;
            unpack2(A0[r], a0d, a0f);
            unpack2(A1[r], a1d, a1f);
            unpack2(A2[r], a2d, a2f);
            float td = __expf(-tt[r]*inv_mud);
            float tf = __expf(-tt[r]*inv_muf);
            float m  = fmaxf(a0d, fmaxf(a1d, a2d));
            float x0 = __expf(a0d-m), x1 = __expf(a1d-m), x2 = __expf(a2d-m);
            float inv = frcp(x0+x1+x2);
            float e0d = x0*inv, e1d = x1*inv;
            m  = fmaxf(a0f, fmaxf(a1f, a2f));
            x0 = __expf(a0f-m); x1 = __expf(a1f-m); x2 = __expf(a2f-m);
            inv = frcp(x0+x1+x2);
            float e0f = x0*inv, e1f = x1*inv;
            float omtd = 1.f - td, omtf = 1.f - tf;
            s_td[idx] = td;
            s_sd[idx] = omtd*e0d;
            s_rd[idx] = omtd*e1d;
            s_Td[idx] = fmaf(omtf, e0f, tf);
            s_Rd[idx] = omtf*e1f;
            s_tf[idx] = tf;
            s_es[idx] = omtf*(e0f+e1f);
        }
    }
    __syncthreads();

    // ---------------- phase 2b: per-layer channel sums ----------------
    if (tid < 240) {
        int arr = tid / 60, l = tid % 60;
        int base = l*42;
        float s = 0.f;
        if (arr == 0) {
            for (int c = 0; c < C_CH; c++) s = fmaf(s_sd[base+c] + s_rd[base+c], S->cs[c], s);
            out[OFF_SDIR + n*60 + l] = s;
        } else if (arr == 1) {
            for (int c = 0; c < C_CH; c++) s = fmaf(s_es[base+c], S->cs[c], s);
            out[OFF_SDIF + n*60 + l] = s;
        } else if (arr == 2) {
            for (int c = 0; c < C_CH; c++) s = fmaf(s_td[base+c], S->cs[c], s);
            out[OFF_TDIR + n*60 + l] = s;
        } else {
            for (int c = 0; c < C_CH; c++) s = fmaf(s_tf[base+c], S->cs[c], s);
            out[OFF_TDIF + n*60 + l] = s;
        }
    }
    __syncthreads();

    // ---------------- phase 3 (backward scan) + phase 4 (forward scan) ----------------
    float* s_rbd = S->arrs + 5*2520;
    float* s_rbf = S->arrs + 6*2520;
    if (tid < C_CH) {
        const int c = tid;
        float rbd = rs_dir, rbf = rs_dif;
        for (int l = 59; l >= 0; l--) {
            int idx = l*42 + c;
            float td = s_td[idx], sd = s_sd[idx], rd = s_rd[idx];
            float Td = s_Td[idx], Rd = s_Rd[idx];
            float dd = frcp_nr(1.f - Rd*rbf);
            s_rbd[idx] = rbd; s_rbf[idx] = rbf;
            float rad = rd + Td*dd*(td*rbd + sd*rbf);
            float raf = Rd + Td*Td*dd*rbf;
            rbd = rad; rbf = raf;
        }
        S->scratch[c] = rbd * S->cs[c];

        float fdir = S->cs[c] * mu_direct * SOLAR_C;
        float fdif = 0.f;
        for (int l = 0; l < 60; l++) {
            int idx = l*42 + c;
            float td = s_td[idx], sd = s_sd[idx], rd = s_rd[idx];
            float Td = s_Td[idx], Rd = s_Rd[idx];
            float rb0 = s_rbd[idx], rb1 = s_rbf[idx];
            float dd = frcp_nr(1.f - Rd*rb1);
            float a  = td * fdir;
            float D  = dd * (Td*fdif + sd*fdir + Rd*rb0*a);
            float U  = rb0*a + rb1*D;
            float up = rd*fdir + Rd*fdif + Td*U;
            float ab = fdir + fdif + U - a - D - up;
            s_td[idx] = a; s_sd[idx] = D; s_rd[idx] = up; s_Td[idx] = ab;
            fdir = a; fdif = D;
        }
    }
    __syncthreads();

    // ---------------- phase 5: flux reductions over channels ----------------
    if (tid < 240) {
        int arr = tid / 60, l = tid % 60;
        const float* src = S->arrs + arr*2520 + l*42;
        float s = 0.f;
        #pragma unroll 6
        for (int c = 0; c < C_CH; c++) s += src[c];
        if (arr == 0)      { out[OFF_FDIR + n*61 + l + 1] = s; if (l == 59) S->scratch[48] = s; }
        else if (arr == 1) { out[OFF_FDIF + n*61 + l + 1] = s; if (l == 59) S->scratch[49] = s; }
        else if (arr == 2) { out[OFF_FUP  + n*61 + l] = s; }
        else               { out[OFF_FABS + n*60 + l] = s; }
    }
    __syncthreads();

    if (tid == 0) {
        out[OFF_FDIR + n*61]      = mu_direct * SOLAR_C * S->cs_sum;
        out[OFF_FDIF + n*61]      = 0.f;
        out[OFF_FUP  + n*61 + 60] = rs_dir * S->scratch[48] + rs_dif * S->scratch[49];
        float rt = 0.f;
        for (int c = 0; c < C_CH; c++) rt += S->scratch[c];
        out[OFF_RTOA + n] = rt;
    }
}

extern "C" void kernel_launch(void* const* d_in, const int* in_sizes, int n_in,
                              void* d_out, int out_size) {
    (void)in_sizes; (void)n_in; (void)out_size;
    cudaFuncSetAttribute(radnet_kernel, cudaFuncAttributeMaxDynamicSharedMemorySize,
                         (int)sizeof(Smem));
    radnet_kernel<<<N_SAMPLES, NTHREADS, sizeof(Smem)>>>(
        (const float*)d_in[0],  (const float*)d_in[1],  (const float*)d_in[2],
        (const float*)d_in[3],  (const float*)d_in[4],  (const float*)d_in[5],
        (const float*)d_in[6],  (const float*)d_in[7],  (const float*)d_in[8],
        (const float*)d_in[9],  (const float*)d_in[10], (const float*)d_in[11],
        (float*)d_out);
}

// round 6
// speedup vs baseline: 1.5522x; 1.2371x over previous
#include <cuda_runtime.h>

// Problem constants (fixed shapes)
#define N_SAMPLES 1024
#define L_LAYERS  60
#define C_CH      42
#define NOUT      336      // C*K
#define LC        2520     // L*C
#define NTHREADS  352
#define SOLAR_C   1361.0f
#define EPSV      1e-6f

// h_t swizzled layout: row stride 80 floats, 16-layer chunk lg at offset lg*20
#define HT_STRIDE 80
#define HT_CHUNK  20

// Output offsets (tuple arrays flattened C-order, concatenated in order)
#define OFF_FDIR 0
#define OFF_FDIF (N_SAMPLES*61)
#define OFF_FUP  (2*N_SAMPLES*61)
#define OFF_FABS (3*N_SAMPLES*61)
#define OFF_RTOA (OFF_FABS + N_SAMPLES*60)
#define OFF_SDIR (OFF_RTOA + N_SAMPLES)
#define OFF_SDIF (OFF_SDIR + N_SAMPLES*60)
#define OFF_TDIR (OFF_SDIF + N_SAMPLES*60)
#define OFF_TDIF (OFF_TDIR + N_SAMPLES*60)

// Smem plane usage over time (8 planes of 2520 floats):
//  0: tau     -> td  -> a          (phase1b -> phase2 -> phase4)
//  1: h_t[0:2520)      -> sd -> D
//  2: h_t[2520:5040)   -> rd -> up
//  3: h_t[5040:5120) (80 fl) -> Td -> abs   (h_t dead before phase 2 writes Td)
//  4:            Rd
//  5:            tf  -> rb_dir
//  6:            es  -> rb_dif
//  7:            (spare)
struct Smem {
    float arrs[8*2520];
    float xs[600];
    float b2[336];
    float b1[64];
    float w1[128];
    float scw1_0[16];
    float beff_dir[16];
    float beff_dif[16];
    float scw2[48];
    float scb2[4];
    float cs[42];
    float cs_sum;
    float scratch[64];
};

__device__ __forceinline__ float softplus_f(float x) {
    return fmaxf(x, 0.f) + __logf(1.f + __expf(-fabsf(x)));
}
__device__ __forceinline__ float frcp(float x) {
    float r; asm("rcp.approx.ftz.f32 %0, %1;" : "=f"(r) : "f"(x)); return r;
}
__device__ __forceinline__ float frcp_nr(float x) {
    float r = frcp(x);
    return r * (2.f - x * r);
}
// ---- packed f32x2 helpers ----
__device__ __forceinline__ unsigned long long dup2(float x) {
    unsigned long long r;
    asm("mov.b64 %0, {%1, %1};" : "=l"(r) : "f"(x));
    return r;
}
__device__ __forceinline__ unsigned long long pack2(float lo, float hi) {
    unsigned long long r;
    asm("mov.b64 %0, {%1, %2};" : "=l"(r) : "f"(lo), "f"(hi));
    return r;
}
__device__ __forceinline__ void unpack2(unsigned long long v, float& lo, float& hi) {
    asm("mov.b64 {%0, %1}, %2;" : "=f"(lo), "=f"(hi) : "l"(v));
}
__device__ __forceinline__ void ffma2(unsigned long long& d, unsigned long long a,
                                      unsigned long long b) {
    asm("fma.rn.f32x2 %0, %1, %2, %0;" : "+l"(d) : "l"(a), "l"(b));
}

__global__ __launch_bounds__(NTHREADS, 2)
void radnet_kernel(const float* __restrict__ x_layers,
                   const float* __restrict__ x_surface,
                   const float* __restrict__ w_mu,
                   const float* __restrict__ w_spec,
                   const float* __restrict__ od_w1,
                   const float* __restrict__ od_b1,
                   const float* __restrict__ od_w2,
                   const float* __restrict__ od_b2,
                   const float* __restrict__ sc_w1,
                   const float* __restrict__ sc_b1,
                   const float* __restrict__ sc_w2,
                   const float* __restrict__ sc_b2,
                   float* __restrict__ out)
{
    extern __shared__ __align__(16) char smem_raw[];
    Smem* S = reinterpret_cast<Smem*>(smem_raw);
    const int tid = threadIdx.x;
    const int n = blockIdx.x;

    const float mu_direct = __ldg(&x_surface[n*5 + 0]);
    const float rs_dir    = __ldg(&x_surface[n*5 + 1]);
    const float rs_dif    = __ldg(&x_surface[n*5 + 2]);
    const float wmu       = __ldg(&w_mu[0]);
    const float mu_dif0   = 1.f / (1.f + __expf(-wmu));
    const float inv_mud   = 1.f / (mu_direct + EPSV);
    const float inv_muf   = 1.f / (mu_dif0 + EPSV);

    // ---------------- setup ----------------
    {
        const float4* xsrc = reinterpret_cast<const float4*>(x_layers + (size_t)n * 600);
        float4* xdst = reinterpret_cast<float4*>(S->xs);
        for (int i = tid; i < 150; i += NTHREADS) xdst[i] = xsrc[i];
        for (int i = tid; i < 336; i += NTHREADS) S->b2[i] = od_b2[i];
        if (tid < 64)  S->b1[tid] = od_b1[tid];
        if (tid >= 64 && tid < 192) S->w1[tid-64] = od_w1[tid-64];
        if (tid >= 192 && tid < 208) {
            int j = tid - 192;
            float w1c = sc_w1[j*2 + 1];
            float b   = sc_b1[j];
            S->scw1_0[j]   = sc_w1[j*2];
            S->beff_dir[j] = fmaf(w1c, mu_direct, b);
            S->beff_dif[j] = fmaf(w1c, mu_dif0, b);
        }
        if (tid >= 208 && tid < 256) S->scw2[tid-208] = sc_w2[tid-208];
        if (tid >= 256 && tid < 259) S->scb2[tid-256] = sc_b2[tid-256];
        if (tid == NTHREADS-1) {
            float m = -1e30f;
            for (int c = 0; c < C_CH; c++) m = fmaxf(m, w_spec[c]);
            float s = 0.f;
            float tmp[C_CH];
            for (int c = 0; c < C_CH; c++) { float e = __expf(w_spec[c]-m); tmp[c] = e; s += e; }
            float inv = 1.f / s;
            float cssum = 0.f;
            for (int c = 0; c < C_CH; c++) { float v = tmp[c]*inv; S->cs[c] = v; cssum += v; }
            S->cs_sum = cssum;
        }
    }
    __syncthreads();

    // ---------------- phase 1a: transposed hidden h_t, swizzled layout ----------------
    // h_t float index: j*80 + (l>>4)*20 + (l&15); l in [60,64) zero-filled.
    float* h_t = S->arrs + 2520;   // 5120 floats (planes 1-2 + 80 floats of plane 3)
    for (int i = tid; i < 4096; i += NTHREADS) {
        int j = i >> 6, l = i & 63;
        float v = 0.f;
        if (l < 60) {
            float pre = fmaf(S->w1[j*2],   S->xs[l*10],
                        fmaf(S->w1[j*2+1], S->xs[l*10+1], S->b1[j]));
            v = softplus_f(pre);
        }
        h_t[j*HT_STRIDE + (l>>4)*HT_CHUNK + (l&15)] = v;
    }
    __syncthreads();

    // ---------------- phase 1b: GEMM, 4 outputs x 16-layer tile per thread ----------------
    float* tau = S->arrs;  // plane 0
    {
        int og = tid >> 2; if (og >= 84) og -= 84;
        const int lg = tid & 3;
        const int c = og >> 1, half = og & 1;
        const int o0 = c*8 + half*4;
        const int l_base = lg << 4;
        const float4* w2r0 = reinterpret_cast<const float4*>(od_w2) + (o0    )*16;
        const float4* w2r1 = w2r0 + 16;
        const float4* w2r2 = w2r0 + 32;
        const float4* w2r3 = w2r0 + 48;
        float b2v[4];
        #pragma unroll
        for (int i = 0; i < 4; i++) b2v[i] = S->b2[o0+i];
        const unsigned hbase = (unsigned)__cvta_generic_to_shared(h_t)
                             + (unsigned)(lg*HT_CHUNK*4);

        #pragma unroll 1
        for (int sub = 0; sub < 2; sub++) {
            const unsigned soff = (unsigned)(sub*32);   // 8 floats per sub-chunk
            unsigned long long acc0[4], acc1[4], acc2[4], acc3[4]; // [output][pair]
            #pragma unroll
            for (int p = 0; p < 4; p++) { acc0[p]=0ull; acc1[p]=0ull; acc2[p]=0ull; acc3[p]=0ull; }
            #pragma unroll 1
            for (int j4 = 0; j4 < 16; j4++) {
                float4 w0 = __ldg(&w2r0[j4]);
                float4 w1 = __ldg(&w2r1[j4]);
                float4 w2 = __ldg(&w2r2[j4]);
                float4 w3 = __ldg(&w2r3[j4]);
                #pragma unroll
                for (int jj = 0; jj < 4; jj++) {
                    const unsigned a = hbase + soff
                                     + (unsigned)((j4*4 + jj)*HT_STRIDE*4);
                    unsigned long long h0, h1, h2, h3;
                    asm("ld.shared.v2.u64 {%0, %1}, [%2];"
                        : "=l"(h0), "=l"(h1) : "r"(a));
                    asm("ld.shared.v2.u64 {%0, %1}, [%2];"
                        : "=l"(h2), "=l"(h3) : "r"(a + 16u));
                    const float s0 = (jj==0)?w0.x:(jj==1)?w0.y:(jj==2)?w0.z:w0.w;
                    const float s1 = (jj==0)?w1.x:(jj==1)?w1.y:(jj==2)?w1.z:w1.w;
                    const float s2 = (jj==0)?w2.x:(jj==1)?w2.y:(jj==2)?w2.z:w2.w;
                    const float s3 = (jj==0)?w3.x:(jj==1)?w3.y:(jj==2)?w3.z:w3.w;
                    unsigned long long d0 = dup2(s0), d1 = dup2(s1);
                    unsigned long long d2 = dup2(s2), d3 = dup2(s3);
                    ffma2(acc0[0], d0, h0); ffma2(acc0[1], d0, h1);
                    ffma2(acc0[2], d0, h2); ffma2(acc0[3], d0, h3);
                    ffma2(acc1[0], d1, h0); ffma2(acc1[1], d1, h1);
                    ffma2(acc1[2], d1, h2); ffma2(acc1[3], d1, h3);
                    ffma2(acc2[0], d2, h0); ffma2(acc2[1], d2, h1);
                    ffma2(acc2[2], d2, h2); ffma2(acc2[3], d2, h3);
                    ffma2(acc3[0], d3, h0); ffma2(acc3[1], d3, h1);
                    ffma2(acc3[2], d3, h2); ffma2(acc3[3], d3, h3);
                }
            }
            // epilogue: per pair p -> layers la, lb
            #pragma unroll
            for (int p = 0; p < 4; p++) {
                const int la = l_base + sub*8 + 2*p;
                const int lb = la + 1;
                float f0a, f0b, f1a, f1b, f2a, f2b, f3a, f3b;
                unpack2(acc0[p], f0a, f0b);
                unpack2(acc1[p], f1a, f1b);
                unpack2(acc2[p], f2a, f2b);
                unpack2(acc3[p], f3a, f3b);
                float va = 0.f, vb = 0.f;
                if (la < 60) {
                    const float* cona = &S->xs[la*10 + 2 + half*4];
                    va = softplus_f(f0a + b2v[0]) * cona[0]
                       + softplus_f(f1a + b2v[1]) * cona[1]
                       + softplus_f(f2a + b2v[2]) * cona[2]
                       + softplus_f(f3a + b2v[3]) * cona[3];
                }
                if (lb < 60) {
                    const float* conb = &S->xs[lb*10 + 2 + half*4];
                    vb = softplus_f(f0b + b2v[0]) * conb[0]
                       + softplus_f(f1b + b2v[1]) * conb[1]
                       + softplus_f(f2b + b2v[2]) * conb[2]
                       + softplus_f(f3b + b2v[3]) * conb[3];
                }
                va += __shfl_xor_sync(0xFFFFFFFFu, va, 4);
                vb += __shfl_xor_sync(0xFFFFFFFFu, vb, 4);
                if (half == 0) {
                    if (la < 60) tau[la*42 + c] = va;
                    if (lb < 60) tau[lb*42 + c] = vb;
                }
            }
        }
    }
    __syncthreads();

    // ---------------- phase 2: per-(l,c) physics + split MLPs (packed {dir,dif}) ----
    float* s_td = S->arrs + 0*2520;
    float* s_sd = S->arrs + 1*2520;
    float* s_rd = S->arrs + 2*2520;
    float* s_Td = S->arrs + 3*2520;
    float* s_Rd = S->arrs + 4*2520;
    float* s_tf = S->arrs + 5*2520;
    float* s_es = S->arrs + 6*2520;
    #pragma unroll 1
    for (int pass = 0; pass < 2; pass++) {
        float tt[4];
        #pragma unroll
        for (int r = 0; r < 4; r++) {
            int idx = tid + (pass*4 + r)*NTHREADS;
            tt[r] = tau[idx < LC ? idx : 0];
        }
        const float b20 = S->scb2[0], b21 = S->scb2[1], b22 = S->scb2[2];
        unsigned long long A0[4], A1[4], A2[4];
        #pragma unroll
        for (int r = 0; r < 4; r++) {
            A0[r] = dup2(b20); A1[r] = dup2(b21); A2[r] = dup2(b22);
        }
        #pragma unroll
        for (int j = 0; j < 16; j++) {
            float w0  = S->scw1_0[j];
            float bd  = S->beff_dir[j];
            float bf  = S->beff_dif[j];
            unsigned long long w20d = dup2(S->scw2[j]);
            unsigned long long w21d = dup2(S->scw2[16+j]);
            unsigned long long w22d = dup2(S->scw2[32+j]);
            #pragma unroll
            for (int r = 0; r < 4; r++) {
                float hp = w0 * tt[r];
                float hd = fmaxf(hp + bd, 0.f);
                float hf = fmaxf(hp + bf, 0.f);
                unsigned long long h2 = pack2(hd, hf);
                ffma2(A0[r], w20d, h2);
                ffma2(A1[r], w21d, h2);
                ffma2(A2[r], w22d, h2);
            }
        }
        #pragma unroll
        for (int r = 0; r < 4; r++) {
            int idx = tid + (pass*4 + r)*NTHREADS;
            if (idx >= LC) break;
            float a0d, a0f, a1d, a1f, a2d, a2f;
            unpack2(A0[r], a0d, a0f);
            unpack2(A1[r], a1d, a1f);
            unpack2(A2[r], a2d, a2f);
            float td = __expf(-tt[r]*inv_mud);
            float tf = __expf(-tt[r]*inv_muf);
            float m  = fmaxf(a0d, fmaxf(a1d, a2d));
            float x0 = __expf(a0d-m), x1 = __expf(a1d-m), x2 = __expf(a2d-m);
            float inv = frcp(x0+x1+x2);
            float e0d = x0*inv, e1d = x1*inv;
            m  = fmaxf(a0f, fmaxf(a1f, a2f));
            x0 = __expf(a0f-m); x1 = __expf(a1f-m); x2 = __expf(a2f-m);
            inv = frcp(x0+x1+x2);
            float e0f = x0*inv, e1f = x1*inv;
            float omtd = 1.f - td, omtf = 1.f - tf;
            s_td[idx] = td;
            s_sd[idx] = omtd*e0d;
            s_rd[idx] = omtd*e1d;
            s_Td[idx] = fmaf(omtf, e0f, tf);
            s_Rd[idx] = omtf*e1f;
            s_tf[idx] = tf;
            s_es[idx] = omtf*(e0f+e1f);
        }
    }
    __syncthreads();

    // ---------------- phase 2b: per-layer channel sums ----------------
    if (tid < 240) {
        int arr = tid / 60, l = tid % 60;
        int base = l*42;
        float s = 0.f;
        if (arr == 0) {
            for (int c = 0; c < C_CH; c++) s = fmaf(s_sd[base+c] + s_rd[base+c], S->cs[c], s);
            out[OFF_SDIR + n*60 + l] = s;
        } else if (arr == 1) {
            for (int c = 0; c < C_CH; c++) s = fmaf(s_es[base+c], S->cs[c], s);
            out[OFF_SDIF + n*60 + l] = s;
        } else if (arr == 2) {
            for (int c = 0; c < C_CH; c++) s = fmaf(s_td[base+c], S->cs[c], s);
            out[OFF_TDIR + n*60 + l] = s;
        } else {
            for (int c = 0; c < C_CH; c++) s = fmaf(s_tf[base+c], S->cs[c], s);
            out[OFF_TDIF + n*60 + l] = s;
        }
    }
    __syncthreads();

    // ---------------- phase 3 (backward scan) + phase 4 (forward scan) ----------------
    float* s_rbd = S->arrs + 5*2520;
    float* s_rbf = S->arrs + 6*2520;
    if (tid < C_CH) {
        const int c = tid;
        float rbd = rs_dir, rbf = rs_dif;
        for (int l = 59; l >= 0; l--) {
            int idx = l*42 + c;
            float td = s_td[idx], sd = s_sd[idx], rd = s_rd[idx];
            float Td = s_Td[idx], Rd = s_Rd[idx];
            float dd = frcp_nr(1.f - Rd*rbf);
            s_rbd[idx] = rbd; s_rbf[idx] = rbf;
            float rad = rd + Td*dd*(td*rbd + sd*rbf);
            float raf = Rd + Td*Td*dd*rbf;
            rbd = rad; rbf = raf;
        }
        S->scratch[c] = rbd * S->cs[c];

        float fdir = S->cs[c] * mu_direct * SOLAR_C;
        float fdif = 0.f;
        for (int l = 0; l < 60; l++) {
            int idx = l*42 + c;
            float td = s_td[idx], sd = s_sd[idx], rd = s_rd[idx];
            float Td = s_Td[idx], Rd = s_Rd[idx];
            float rb0 = s_rbd[idx], rb1 = s_rbf[idx];
            float dd = frcp_nr(1.f - Rd*rb1);
            float a  = td * fdir;
            float D  = dd * (Td*fdif + sd*fdir + Rd*rb0*a);
            float U  = rb0*a + rb1*D;
            float up = rd*fdir + Rd*fdif + Td*U;
            float ab = fdir + fdif + U - a - D - up;
            s_td[idx] = a; s_sd[idx] = D; s_rd[idx] = up; s_Td[idx] = ab;
            fdir = a; fdif = D;
        }
    }
    __syncthreads();

    // ---------------- phase 5: flux reductions over channels ----------------
    if (tid < 240) {
        int arr = tid / 60, l = tid % 60;
        const float* src = S->arrs + arr*2520 + l*42;
        float s = 0.f;
        #pragma unroll 6
        for (int c = 0; c < C_CH; c++) s += src[c];
        if (arr == 0)      { out[OFF_FDIR + n*61 + l + 1] = s; if (l == 59) S->scratch[48] = s; }
        else if (arr == 1) { out[OFF_FDIF + n*61 + l + 1] = s; if (l == 59) S->scratch[49] = s; }
        else if (arr == 2) { out[OFF_FUP  + n*61 + l] = s; }
        else               { out[OFF_FABS + n*60 + l] = s; }
    }
    __syncthreads();

    if (tid == 0) {
        out[OFF_FDIR + n*61]      = mu_direct * SOLAR_C * S->cs_sum;
        out[OFF_FDIF + n*61]      = 0.f;
        out[OFF_FUP  + n*61 + 60] = rs_dir * S->scratch[48] + rs_dif * S->scratch[49];
        float rt = 0.f;
        for (int c = 0; c < C_CH; c++) rt += S->scratch[c];
        out[OFF_RTOA + n] = rt;
    }
}

extern "C" void kernel_launch(void* const* d_in, const int* in_sizes, int n_in,
                              void* d_out, int out_size) {
    (void)in_sizes; (void)n_in; (void)out_size;
    cudaFuncSetAttribute(radnet_kernel, cudaFuncAttributeMaxDynamicSharedMemorySize,
                         (int)sizeof(Smem));
    radnet_kernel<<<N_SAMPLES, NTHREADS, sizeof(Smem)>>>(
        (const float*)d_in[0],  (const float*)d_in[1],  (const float*)d_in[2],
        (const float*)d_in[3],  (const float*)d_in[4],  (const float*)d_in[5],
        (const float*)d_in[6],  (const float*)d_in[7],  (const float*)d_in[8],
        (const float*)d_in[9],  (const float*)d_in[10], (const float*)d_in[11],
        (float*)d_out);
}